// round 4
// baseline (speedup 1.0000x reference)
#include <cuda_runtime.h>
#include <cuda_bf16.h>
#include <math.h>

// Problem constants
#define BATCH   16384
#define FDIM    256
#define RULES   32
#define CDIM    16
#define H1DIM   128
#define H2DIM   32
#define G1DIM   256
#define G2DIM   64

// ---------------- device scratch (no allocations allowed) ----------------
__device__ float g_Wf1T[FDIM * H1DIM];            // [f][o]
__device__ float g_Wf2T[H1DIM * H2DIM];           // [k][p]
__device__ float g_Wc1T[RULES * FDIM * G1DIM];    // [r][f][g]   8 MB
__device__ float g_Wc2T[RULES * G1DIM * G2DIM];   // [r][h][g]   2 MB
__device__ float g_Wc3T[RULES * G2DIM * CDIM];    // [r][g][c]
__device__ float g_fs[BATCH * RULES];             // [b][r] fs_ini
__device__ float g_fire_scratch[BATCH * RULES];   // fallback if out_size small
__device__ float g_c3[(size_t)RULES * BATCH * CDIM]; // [r][b][c]  33.5 MB

// ---------------- batched tiled transpose: dst[b][j][i] = src[b][i][j] ----
__global__ void transpose_k(const float* __restrict__ src, float* __restrict__ dst,
                            int rows, int cols) {
    __shared__ float tile[32][33];
    int batch = blockIdx.z;
    src += (size_t)batch * rows * cols;
    dst += (size_t)batch * rows * cols;
    int x = blockIdx.x * 32 + threadIdx.x;   // col in src
    int y0 = blockIdx.y * 32;
    for (int j = threadIdx.y; j < 32; j += 8) {
        int y = y0 + j;
        if (y < rows && x < cols) tile[j][threadIdx.x] = src[(size_t)y * cols + x];
    }
    __syncthreads();
    int xo = blockIdx.y * 32 + threadIdx.x;  // row in src
    for (int j = threadIdx.y; j < 32; j += 8) {
        int yo = blockIdx.x * 32 + j;        // col in src
        if (yo < cols && xo < rows) dst[(size_t)yo * rows + xo] = tile[threadIdx.x][j];
    }
}

// ---------------- fused FS kernel: per (rule, 128-batch tile) -------------
// h1 = relu(mem @ Wf1^T + bf1); h2 = relu(h1 @ Wf2^T + bf2); fs = relu(h2.Wf3 + bf3)
// smem floats: proto 256 | inv 256 | bf1 128 | bf2 32 | wf3 32 | wf2t 4096 |
//              As 2048 | Bs 2048 | h1s 128*132 = 16896   -> total 25792 (103168 B)
#define FS_SMEM_FLOATS 25792
__global__ __launch_bounds__(256, 2)
void fs_kernel(const float* __restrict__ data, const float* __restrict__ proto,
               const float* __restrict__ var, const float* __restrict__ bf1,
               const float* __restrict__ bf2, const float* __restrict__ Wf3,
               const float* __restrict__ bf3) {
    extern __shared__ float sm[];
    float* proto_s = sm;
    float* inv_s   = sm + 256;
    float* bf1_s   = sm + 512;
    float* bf2_s   = sm + 640;
    float* wf3_s   = sm + 672;
    float* wf2t_s  = sm + 704;
    float* As      = sm + 4800;   // [16][128]
    float* Bs      = sm + 6848;   // [16][128]
    float* h1s     = sm + 8896;   // [128][132]

    const int t  = threadIdx.x;
    const int r  = blockIdx.y;
    const int b0 = blockIdx.x << 7;

    {
        float v = var[r * FDIM + t];
        v = fminf(fmaxf(v, 1e-4f), 0.1f);
        inv_s[t]   = 1.0f / (2.0f * v * v);
        proto_s[t] = proto[r * FDIM + t];
    }
    if (t < 128) bf1_s[t] = bf1[t];
    if (t < 32)  { bf2_s[t] = bf2[t]; wf3_s[t] = Wf3[t]; }
    #pragma unroll 4
    for (int idx = t; idx < H1DIM * H2DIM; idx += 256) wf2t_s[idx] = g_Wf2T[idx];
    __syncthreads();

    const int tx = t & 15, ty = t >> 4;
    const int li = t >> 1, lk = (t & 1) << 3;
    const int kb = t >> 4, ob = (t & 15) << 3;
    const float* dp_base = data + (size_t)(b0 + li) * FDIM + lk;

    float acc[8][8];
    #pragma unroll
    for (int i = 0; i < 8; i++)
        #pragma unroll
        for (int j = 0; j < 8; j++) acc[i][j] = 0.0f;

    // -------- software-pipelined GEMM1: prefetch tile k+1 LDGs during tile k FFMAs
    float dv[8];
    float4 wv0, wv1;
    {   // prologue: tile 0
        float4 v0 = *(const float4*)(dp_base);
        float4 v1 = *(const float4*)(dp_base + 4);
        dv[0]=v0.x; dv[1]=v0.y; dv[2]=v0.z; dv[3]=v0.w;
        dv[4]=v1.x; dv[5]=v1.y; dv[6]=v1.z; dv[7]=v1.w;
        const float* wp = g_Wf1T + (size_t)kb * H1DIM + ob;
        wv0 = *(const float4*)wp; wv1 = *(const float4*)(wp + 4);
    }
    for (int k0 = 0; k0 < FDIM; k0 += 16) {
        // store current tile (exp fused here; membership never hits HBM)
        #pragma unroll
        for (int j = 0; j < 8; j++) {
            int kf = k0 + lk + j;
            float d = dv[j] - proto_s[kf];
            As[(lk + j) * 128 + li] = __expf(-d * d * inv_s[kf]);
        }
        *(float4*)&Bs[kb * 128 + ob]     = wv0;
        *(float4*)&Bs[kb * 128 + ob + 4] = wv1;
        __syncthreads();
        // prefetch next tile
        if (k0 + 16 < FDIM) {
            float4 v0 = *(const float4*)(dp_base + k0 + 16);
            float4 v1 = *(const float4*)(dp_base + k0 + 20);
            dv[0]=v0.x; dv[1]=v0.y; dv[2]=v0.z; dv[3]=v0.w;
            dv[4]=v1.x; dv[5]=v1.y; dv[6]=v1.z; dv[7]=v1.w;
            const float* wp = g_Wf1T + (size_t)(k0 + 16 + kb) * H1DIM + ob;
            wv0 = *(const float4*)wp; wv1 = *(const float4*)(wp + 4);
        }
        #pragma unroll
        for (int k = 0; k < 16; k++) {
            float a[8], b[8];
            *(float4*)&a[0] = *(const float4*)&As[k * 128 + ty * 8];
            *(float4*)&a[4] = *(const float4*)&As[k * 128 + ty * 8 + 4];
            *(float4*)&b[0] = *(const float4*)&Bs[k * 128 + tx * 8];
            *(float4*)&b[4] = *(const float4*)&Bs[k * 128 + tx * 8 + 4];
            #pragma unroll
            for (int ii = 0; ii < 8; ii++)
                #pragma unroll
                for (int jj = 0; jj < 8; jj++)
                    acc[ii][jj] += a[ii] * b[jj];
        }
        __syncthreads();
    }

    // bias + relu -> h1s
    #pragma unroll
    for (int ii = 0; ii < 8; ii++)
        #pragma unroll
        for (int jj = 0; jj < 8; jj++) {
            float h = acc[ii][jj] + bf1_s[tx * 8 + jj];
            h1s[(ty * 8 + ii) * 132 + tx * 8 + jj] = fmaxf(h, 0.0f);
        }
    __syncthreads();

    // GEMM2: h2[li][ph..ph+15], K = 128
    const int ph = (t & 1) << 4;
    float acc2[16];
    #pragma unroll
    for (int j = 0; j < 16; j++) acc2[j] = bf2_s[ph + j];
    for (int k = 0; k < H1DIM; k++) {
        float a = h1s[li * 132 + k];
        #pragma unroll
        for (int j = 0; j < 16; j += 4) {
            float4 w = *(const float4*)&wf2t_s[k * H2DIM + ph + j];
            acc2[j + 0] += a * w.x; acc2[j + 1] += a * w.y;
            acc2[j + 2] += a * w.z; acc2[j + 3] += a * w.w;
        }
    }
    float fsum = 0.0f;
    #pragma unroll
    for (int j = 0; j < 16; j++) fsum += fmaxf(acc2[j], 0.0f) * wf3_s[ph + j];
    fsum += __shfl_xor_sync(0xffffffffu, fsum, 1);
    if ((t & 1) == 0)
        g_fs[(size_t)(b0 + li) * RULES + r] = fmaxf(fsum + bf3[0], 0.0f);
}

// ---------------- softmax over rules: fire[b][r] --------------------------
__global__ void softmax_kernel(float* __restrict__ fire_out) {
    int b = blockIdx.x * blockDim.x + threadIdx.x;
    if (b >= BATCH) return;
    const float* f = g_fs + (size_t)b * RULES;
    float v[RULES];
    #pragma unroll
    for (int j = 0; j < RULES; j += 4) {
        float4 t4 = *(const float4*)&f[j];
        v[j] = t4.x; v[j + 1] = t4.y; v[j + 2] = t4.z; v[j + 3] = t4.w;
    }
    float m = v[0];
    #pragma unroll
    for (int j = 1; j < RULES; j++) m = fmaxf(m, v[j]);
    float s = 0.0f;
    #pragma unroll
    for (int j = 0; j < RULES; j++) { v[j] = __expf(v[j] - m); s += v[j]; }
    float inv = 1.0f / s;
    float* o = fire_out + (size_t)b * RULES;
    #pragma unroll
    for (int j = 0; j < RULES; j += 4) {
        float4 t4 = make_float4(v[j] * inv, v[j + 1] * inv, v[j + 2] * inv, v[j + 3] * inv);
        *(float4*)&o[j] = t4;
    }
}

// ---------------- fused consequent kernel: per (rule, 128-batch tile) -----
// Restructured for 2 CTAs/SM (104 KB smem):
//   c1 computed one 128-col half at a time -> c1s_half [128][129]
//   L2 accumulators acc2[32] carried in registers across halves (same k order)
//   Wc2T streamed in 64-row chunks; L3 from registers via shfl pair-combine
// smem floats: bc1 256 | bc2 64 | bc3 16 | wc3t 1024 | As 2048 | Bs 2048 |
//              wc2t_chunk 4096 | c1s_half 128*129 = 16512  -> total 26064
#define CONS_SMEM_FLOATS 26064
__global__ __launch_bounds__(256, 2)
void cons_kernel(const float* __restrict__ data, const float* __restrict__ bc1,
                 const float* __restrict__ bc2, const float* __restrict__ bc3) {
    extern __shared__ float sm[];
    float* bc1s   = sm;            // 256
    float* bc2s   = sm + 256;      // 64
    float* bc3s   = sm + 320;      // 16
    float* wc3t_s = sm + 336;      // [64][16] = 1024
    float* As     = sm + 1360;     // [16][128]
    float* Bs     = sm + 3408;     // [16][128]
    float* wc2t_s = sm + 5456;     // [64][64] chunk = 4096
    float* c1s    = sm + 9552;     // [128][129] = 16512

    const int t  = threadIdx.x;
    const int r  = blockIdx.y;
    const int b0 = blockIdx.x << 7;

    bc1s[t] = bc1[r * G1DIM + t];
    if (t < 64) bc2s[t] = bc2[r * G2DIM + t];
    if (t < 16) bc3s[t] = bc3[r * CDIM + t];
    for (int idx = t; idx < G2DIM * CDIM; idx += 256)
        wc3t_s[idx] = g_Wc3T[(size_t)r * G2DIM * CDIM + idx];
    __syncthreads();

    const int tx = t & 15, ty = t >> 4;
    const int li = t >> 1, lk = (t & 1) << 3;
    const int kb = t >> 4, ob = (t & 15) << 3;
    const int gh = (t & 1) << 5;                 // L2/L3 col group: 0 or 32
    const float* wc1t = g_Wc1T + (size_t)r * FDIM * G1DIM;
    const float* wc2t = g_Wc2T + (size_t)r * G1DIM * G2DIM;
    const float* dp_base = data + (size_t)(b0 + li) * FDIM + lk;

    // L2 accumulators (c2 row li, cols gh..gh+31), carried across both halves
    float acc2[32];
    #pragma unroll
    for (int j = 0; j < 32; j++) acc2[j] = bc2s[gh + j];

    for (int half = 0; half < 2; half++) {
        // ---- L1 GEMM: output cols [half*128, +128), K = 256, pipelined LDGs
        float acc[8][8];
        #pragma unroll
        for (int i = 0; i < 8; i++)
            #pragma unroll
            for (int j = 0; j < 8; j++) acc[i][j] = 0.0f;

        float dv[8];
        float4 wv0, wv1;
        {   // prologue: tile 0
            float4 v0 = *(const float4*)(dp_base);
            float4 v1 = *(const float4*)(dp_base + 4);
            dv[0]=v0.x; dv[1]=v0.y; dv[2]=v0.z; dv[3]=v0.w;
            dv[4]=v1.x; dv[5]=v1.y; dv[6]=v1.z; dv[7]=v1.w;
            const float* wp = wc1t + (size_t)kb * G1DIM + (half << 7) + ob;
            wv0 = *(const float4*)wp; wv1 = *(const float4*)(wp + 4);
        }
        for (int k0 = 0; k0 < FDIM; k0 += 16) {
            #pragma unroll
            for (int j = 0; j < 8; j++) As[(lk + j) * 128 + li] = dv[j];
            *(float4*)&Bs[kb * 128 + ob]     = wv0;
            *(float4*)&Bs[kb * 128 + ob + 4] = wv1;
            __syncthreads();
            if (k0 + 16 < FDIM) {
                float4 v0 = *(const float4*)(dp_base + k0 + 16);
                float4 v1 = *(const float4*)(dp_base + k0 + 20);
                dv[0]=v0.x; dv[1]=v0.y; dv[2]=v0.z; dv[3]=v0.w;
                dv[4]=v1.x; dv[5]=v1.y; dv[6]=v1.z; dv[7]=v1.w;
                const float* wp = wc1t + (size_t)(k0 + 16 + kb) * G1DIM + (half << 7) + ob;
                wv0 = *(const float4*)wp; wv1 = *(const float4*)(wp + 4);
            }
            #pragma unroll
            for (int k = 0; k < 16; k++) {
                float a[8], b[8];
                *(float4*)&a[0] = *(const float4*)&As[k * 128 + ty * 8];
                *(float4*)&a[4] = *(const float4*)&As[k * 128 + ty * 8 + 4];
                *(float4*)&b[0] = *(const float4*)&Bs[k * 128 + tx * 8];
                *(float4*)&b[4] = *(const float4*)&Bs[k * 128 + tx * 8 + 4];
                #pragma unroll
                for (int ii = 0; ii < 8; ii++)
                    #pragma unroll
                    for (int jj = 0; jj < 8; jj++)
                        acc[ii][jj] += a[ii] * b[jj];
            }
            __syncthreads();
        }
        // epilogue: bias + ELU -> c1s (this half's 128 cols live at col-offset 0..127)
        #pragma unroll
        for (int ii = 0; ii < 8; ii++)
            #pragma unroll
            for (int jj = 0; jj < 8; jj++) {
                float x = acc[ii][jj] + bc1s[(half << 7) + tx * 8 + jj];
                c1s[(ty * 8 + ii) * 129 + tx * 8 + jj] =
                    (x > 0.0f) ? x : (__expf(x) - 1.0f);
            }
        __syncthreads();   // c1s half fully written before L2 reads

        // ---- L2 partial: k range [half*128, +128) in two 64-row weight chunks
        for (int kc = 0; kc < 2; kc++) {
            const int kg = (half << 7) + (kc << 6);   // global k base of chunk
            for (int idx = t; idx < 64 * G2DIM; idx += 256)
                wc2t_s[idx] = wc2t[(size_t)kg * G2DIM + idx];
            __syncthreads();
            for (int k = 0; k < 64; k++) {
                float a = c1s[li * 129 + (kc << 6) + k];
                #pragma unroll
                for (int j = 0; j < 32; j += 4) {
                    float4 w = *(const float4*)&wc2t_s[k * G2DIM + gh + j];
                    acc2[j + 0] += a * w.x; acc2[j + 1] += a * w.y;
                    acc2[j + 2] += a * w.z; acc2[j + 3] += a * w.w;
                }
            }
            __syncthreads();   // before wc2t_s overwrite / c1s overwrite next half
        }
    }

    // ---- ELU on c2 (full K=256 accumulated, bias included at init) ----
    #pragma unroll
    for (int j = 0; j < 32; j++)
        acc2[j] = (acc2[j] > 0.0f) ? acc2[j] : (__expf(acc2[j]) - 1.0f);

    // ---- L3 from registers: c3[li][c] = sum_g c2[li][g] * Wc3T[g][c] ----
    float acc3[16];
    #pragma unroll
    for (int c = 0; c < 16; c++) acc3[c] = 0.0f;
    for (int g = 0; g < 32; g++) {
        float a = acc2[g];
        const float* wrow = &wc3t_s[(gh + g) * CDIM];
        #pragma unroll
        for (int c = 0; c < 16; c += 4) {
            float4 w = *(const float4*)&wrow[c];
            acc3[c + 0] += a * w.x; acc3[c + 1] += a * w.y;
            acc3[c + 2] += a * w.z; acc3[c + 3] += a * w.w;
        }
    }
    // combine the two g-halves held by the even/odd thread pair
    #pragma unroll
    for (int c = 0; c < 16; c++)
        acc3[c] += __shfl_xor_sync(0xffffffffu, acc3[c], 1);

    const int ch = (t & 1) << 3;
    float* op = g_c3 + ((size_t)((r << 14) + b0 + li)) * CDIM + ch;
    float4 o0 = make_float4(fmaxf(acc3[ch + 0] + bc3s[ch + 0], 0.f),
                            fmaxf(acc3[ch + 1] + bc3s[ch + 1], 0.f),
                            fmaxf(acc3[ch + 2] + bc3s[ch + 2], 0.f),
                            fmaxf(acc3[ch + 3] + bc3s[ch + 3], 0.f));
    float4 o1 = make_float4(fmaxf(acc3[ch + 4] + bc3s[ch + 4], 0.f),
                            fmaxf(acc3[ch + 5] + bc3s[ch + 5], 0.f),
                            fmaxf(acc3[ch + 6] + bc3s[ch + 6], 0.f),
                            fmaxf(acc3[ch + 7] + bc3s[ch + 7], 0.f));
    *(float4*)op       = o0;
    *(float4*)(op + 4) = o1;
}

// ---------------- weighted reduction: out[b][c] = sum_r fire[b][r]*c3[r][b][c]
__global__ void out_kernel(float* __restrict__ out, const float* __restrict__ fire) {
    int idx = blockIdx.x * blockDim.x + threadIdx.x;   // B*C/4 = 65536 threads
    int b  = idx >> 2;
    int c4 = (idx & 3) << 2;
    const float* fb = fire + (size_t)b * RULES;
    float4 acc = make_float4(0.f, 0.f, 0.f, 0.f);
    #pragma unroll
    for (int r = 0; r < RULES; r++) {
        float w = fb[r];
        float4 v = *(const float4*)&g_c3[((size_t)(r << 14) + b) * CDIM + c4];
        acc.x += w * v.x; acc.y += w * v.y; acc.z += w * v.z; acc.w += w * v.w;
    }
    *(float4*)&out[(size_t)b * CDIM + c4] = acc;
}

// ---------------- launch --------------------------------------------------
extern "C" void kernel_launch(void* const* d_in, const int* in_sizes, int n_in,
                              void* d_out, int out_size) {
    const float* data  = (const float*)d_in[0];
    const float* proto = (const float*)d_in[1];
    const float* var   = (const float*)d_in[2];
    const float* Wf1   = (const float*)d_in[3];
    const float* bf1   = (const float*)d_in[4];
    const float* Wf2   = (const float*)d_in[5];
    const float* bf2   = (const float*)d_in[6];
    const float* Wf3   = (const float*)d_in[7];
    const float* bf3   = (const float*)d_in[8];
    const float* Wc1   = (const float*)d_in[9];
    const float* bc1   = (const float*)d_in[10];
    const float* Wc2   = (const float*)d_in[11];
    const float* bc2   = (const float*)d_in[12];
    const float* Wc3   = (const float*)d_in[13];
    const float* bc3   = (const float*)d_in[14];
    float* out = (float*)d_out;

    // output layout: outputs [B,C] flattened first, then fire_strength [B,R]
    float* fire_dst;
    if (out_size >= BATCH * CDIM + BATCH * RULES) {
        fire_dst = out + BATCH * CDIM;
    } else {
        // fallback: only outputs requested; keep fire in scratch
        cudaGetSymbolAddress((void**)&fire_dst, g_fire_scratch);
    }

    // opt-in large dynamic smem (idempotent; host-side, not stream-ordered)
    cudaFuncSetAttribute(fs_kernel, cudaFuncAttributeMaxDynamicSharedMemorySize,
                         FS_SMEM_FLOATS * 4);
    cudaFuncSetAttribute(cons_kernel, cudaFuncAttributeMaxDynamicSharedMemorySize,
                         CONS_SMEM_FLOATS * 4);

    float *wf1t, *wf2t, *wc1t, *wc2t, *wc3t;
    cudaGetSymbolAddress((void**)&wf1t, g_Wf1T);
    cudaGetSymbolAddress((void**)&wf2t, g_Wf2T);
    cudaGetSymbolAddress((void**)&wc1t, g_Wc1T);
    cudaGetSymbolAddress((void**)&wc2t, g_Wc2T);
    cudaGetSymbolAddress((void**)&wc3t, g_Wc3T);

    dim3 tb(32, 8);
    transpose_k<<<dim3(8, 4, 1),  tb>>>(Wf1, wf1t, H1DIM, FDIM);
    transpose_k<<<dim3(4, 1, 1),  tb>>>(Wf2, wf2t, H2DIM, H1DIM);
    transpose_k<<<dim3(8, 8, 32), tb>>>(Wc1, wc1t, G1DIM, FDIM);
    transpose_k<<<dim3(8, 2, 32), tb>>>(Wc2, wc2t, G2DIM, G1DIM);
    transpose_k<<<dim3(2, 1, 32), tb>>>(Wc3, wc3t, CDIM, G2DIM);

    fs_kernel<<<dim3(BATCH / 128, RULES), 256, FS_SMEM_FLOATS * 4>>>(
        data, proto, var, bf1, bf2, Wf3, bf3);
    softmax_kernel<<<BATCH / 256, 256>>>(fire_dst);
    cons_kernel<<<dim3(BATCH / 128, RULES), 256, CONS_SMEM_FLOATS * 4>>>(
        data, bc1, bc2, bc3);
    out_kernel<<<(BATCH * CDIM / 4) / 256, 256>>>(out, fire_dst);
}

// round 5
// speedup vs baseline: 1.6296x; 1.6296x over previous
#include <cuda_runtime.h>
#include <cuda_bf16.h>
#include <math.h>
#include <stdint.h>

// Problem constants
#define BATCH   16384
#define FDIM    256
#define RULES   32
#define CDIM    16
#define H1DIM   128
#define H2DIM   32
#define G1DIM   256
#define G2DIM   64

// ---------------- device scratch (no allocations allowed) ----------------
__device__ float g_Wf1T[FDIM * H1DIM];            // [f][o]
__device__ float g_Wf2T[H1DIM * H2DIM];           // [k][p]
__device__ float g_Wc1T[RULES * FDIM * G1DIM];    // [r][f][g]   8 MB
__device__ float g_Wc2T[RULES * G1DIM * G2DIM];   // [r][h][g]   2 MB
__device__ float g_Wc3T[RULES * G2DIM * CDIM];    // [r][g][c]
__device__ float g_fs[BATCH * RULES];             // [b][r] fs_ini
__device__ float g_fire_scratch[BATCH * RULES];   // fallback if out_size small
__device__ float g_c3[(size_t)RULES * BATCH * CDIM]; // [r][b][c]  33.5 MB

// tf32 round-to-nearest (rna) — halves error vs HW truncation in mma operands
__device__ __forceinline__ float f2tf32(float x) {
    asm("cvt.rna.tf32.f32 %0, %0;" : "+f"(x));
    return x;
}

// m16n8k8 tf32 warp MMA, accumulate in place
#define MMA_TF32(C, A, B0, B1) \
    asm volatile("mma.sync.aligned.m16n8k8.row.col.f32.tf32.tf32.f32 " \
        "{%0,%1,%2,%3}, {%4,%5,%6,%7}, {%8,%9}, {%0,%1,%2,%3};" \
        : "+f"((C)[0]), "+f"((C)[1]), "+f"((C)[2]), "+f"((C)[3]) \
        : "r"((A)[0]), "r"((A)[1]), "r"((A)[2]), "r"((A)[3]), "r"(B0), "r"(B1))

// Smem tile strides for the mma GEMMs
#define AST 20    // As row-major [128][20]
#define BST 132   // Bs k-major  [16][132]

// ---------------- batched tiled transpose: dst[b][j][i] = src[b][i][j] ----
__global__ void transpose_k(const float* __restrict__ src, float* __restrict__ dst,
                            int rows, int cols) {
    __shared__ float tile[32][33];
    int batch = blockIdx.z;
    src += (size_t)batch * rows * cols;
    dst += (size_t)batch * rows * cols;
    int x = blockIdx.x * 32 + threadIdx.x;   // col in src
    int y0 = blockIdx.y * 32;
    for (int j = threadIdx.y; j < 32; j += 8) {
        int y = y0 + j;
        if (y < rows && x < cols) tile[j][threadIdx.x] = src[(size_t)y * cols + x];
    }
    __syncthreads();
    int xo = blockIdx.y * 32 + threadIdx.x;  // row in src
    for (int j = threadIdx.y; j < 32; j += 8) {
        int yo = blockIdx.x * 32 + j;        // col in src
        if (yo < cols && xo < rows) dst[(size_t)yo * rows + xo] = tile[threadIdx.x][j];
    }
}

// ---------------- fused FS kernel: per (rule, 128-batch tile) -------------
// GEMM1 (mem @ Wf1^T) now on tf32 tensor cores; GEMM2/fs unchanged (verified).
// smem floats: proto 256|inv 256|bf1 128|bf2 32|wf3 32|wf2t 4096 | As 2560 |
//              Bs 2112 | h1s 128*132=16896  -> total 26368 (105472 B)
#define FS_SMEM_FLOATS 26368
__global__ __launch_bounds__(256, 2)
void fs_kernel(const float* __restrict__ data, const float* __restrict__ proto,
               const float* __restrict__ var, const float* __restrict__ bf1,
               const float* __restrict__ bf2, const float* __restrict__ Wf3,
               const float* __restrict__ bf3) {
    extern __shared__ float sm[];
    float* proto_s = sm;
    float* inv_s   = sm + 256;
    float* bf1_s   = sm + 512;
    float* bf2_s   = sm + 640;
    float* wf3_s   = sm + 672;
    float* wf2t_s  = sm + 704;
    float* As      = sm + 4800;   // [128][20] row-major
    float* Bs      = sm + 7360;   // [16][132] k-major
    float* h1s     = sm + 9472;   // [128][132]

    const int t  = threadIdx.x;
    const int r  = blockIdx.y;
    const int b0 = blockIdx.x << 7;

    {
        float v = var[r * FDIM + t];
        v = fminf(fmaxf(v, 1e-4f), 0.1f);
        inv_s[t]   = 1.0f / (2.0f * v * v);
        proto_s[t] = proto[r * FDIM + t];
    }
    if (t < 128) bf1_s[t] = bf1[t];
    if (t < 32)  { bf2_s[t] = bf2[t]; wf3_s[t] = Wf3[t]; }
    #pragma unroll 4
    for (int idx = t; idx < H1DIM * H2DIM; idx += 256) wf2t_s[idx] = g_Wf2T[idx];
    __syncthreads();

    const int li = t >> 1, lk = (t & 1) << 3;   // staging: row li, k lk..lk+7
    const int kb = t >> 4, ob = (t & 15) << 3;  // staging: B row kb, cols ob..ob+7
    const int lane = t & 31, wid = t >> 5;
    const int wr = wid & 3, wc = wid >> 1 & 0 ? 0 : (wid >> 2); // wc = wid>>2
    const int gid = lane >> 2, tig = lane & 3;
    const float* dp_base = data + (size_t)(b0 + li) * FDIM + lk;

    float acc[2][8][4];
    #pragma unroll
    for (int i = 0; i < 2; i++)
        #pragma unroll
        for (int j = 0; j < 8; j++)
            #pragma unroll
            for (int q = 0; q < 4; q++) acc[i][j][q] = 0.0f;

    // pipelined staging regs
    float dv[8];
    float4 wv0, wv1;
    {   // prologue
        float4 v0 = *(const float4*)(dp_base);
        float4 v1 = *(const float4*)(dp_base + 4);
        dv[0]=v0.x; dv[1]=v0.y; dv[2]=v0.z; dv[3]=v0.w;
        dv[4]=v1.x; dv[5]=v1.y; dv[6]=v1.z; dv[7]=v1.w;
        const float* wp = g_Wf1T + (size_t)kb * H1DIM + ob;
        wv0 = *(const float4*)wp; wv1 = *(const float4*)(wp + 4);
    }
    for (int k0 = 0; k0 < FDIM; k0 += 16) {
        // store current tile: membership (exp fused), tf32-rounded, row-major
        {
            float m[8];
            #pragma unroll
            for (int j = 0; j < 8; j++) {
                int kf = k0 + lk + j;
                float d = dv[j] - proto_s[kf];
                m[j] = f2tf32(__expf(-d * d * inv_s[kf]));
            }
            *(float4*)&As[li * AST + lk]     = make_float4(m[0], m[1], m[2], m[3]);
            *(float4*)&As[li * AST + lk + 4] = make_float4(m[4], m[5], m[6], m[7]);
        }
        {
            float4 w0 = make_float4(f2tf32(wv0.x), f2tf32(wv0.y), f2tf32(wv0.z), f2tf32(wv0.w));
            float4 w1 = make_float4(f2tf32(wv1.x), f2tf32(wv1.y), f2tf32(wv1.z), f2tf32(wv1.w));
            *(float4*)&Bs[kb * BST + ob]     = w0;
            *(float4*)&Bs[kb * BST + ob + 4] = w1;
        }
        __syncthreads();
        // prefetch next tile
        if (k0 + 16 < FDIM) {
            float4 v0 = *(const float4*)(dp_base + k0 + 16);
            float4 v1 = *(const float4*)(dp_base + k0 + 20);
            dv[0]=v0.x; dv[1]=v0.y; dv[2]=v0.z; dv[3]=v0.w;
            dv[4]=v1.x; dv[5]=v1.y; dv[6]=v1.z; dv[7]=v1.w;
            const float* wp = g_Wf1T + (size_t)(k0 + 16 + kb) * H1DIM + ob;
            wv0 = *(const float4*)wp; wv1 = *(const float4*)(wp + 4);
        }
        // tensor-core compute: 2 k-steps of 8
        #pragma unroll
        for (int ks = 0; ks < 16; ks += 8) {
            uint32_t a[2][4];
            #pragma unroll
            for (int mt = 0; mt < 2; mt++) {
                const float* ap = &As[(wr * 32 + mt * 16 + gid) * AST + ks + tig];
                a[mt][0] = __float_as_uint(ap[0]);
                a[mt][1] = __float_as_uint(ap[8 * AST]);
                a[mt][2] = __float_as_uint(ap[4]);
                a[mt][3] = __float_as_uint(ap[8 * AST + 4]);
            }
            #pragma unroll
            for (int nt = 0; nt < 8; nt++) {
                int n0 = wc * 64 + nt * 8 + gid;
                uint32_t bb0 = __float_as_uint(Bs[(ks + tig) * BST + n0]);
                uint32_t bb1 = __float_as_uint(Bs[(ks + tig + 4) * BST + n0]);
                MMA_TF32(acc[0][nt], a[0], bb0, bb1);
                MMA_TF32(acc[1][nt], a[1], bb0, bb1);
            }
        }
        __syncthreads();
    }

    // epilogue: bias + relu -> h1s  (fragment C layout: rows g,g+8; cols 2*tig,+1)
    #pragma unroll
    for (int mt = 0; mt < 2; mt++) {
        int r0 = wr * 32 + mt * 16 + gid;
        #pragma unroll
        for (int nt = 0; nt < 8; nt++) {
            int c0 = wc * 64 + nt * 8 + 2 * tig;
            h1s[r0 * 132 + c0]           = fmaxf(acc[mt][nt][0] + bf1_s[c0], 0.0f);
            h1s[r0 * 132 + c0 + 1]       = fmaxf(acc[mt][nt][1] + bf1_s[c0 + 1], 0.0f);
            h1s[(r0 + 8) * 132 + c0]     = fmaxf(acc[mt][nt][2] + bf1_s[c0], 0.0f);
            h1s[(r0 + 8) * 132 + c0 + 1] = fmaxf(acc[mt][nt][3] + bf1_s[c0 + 1], 0.0f);
        }
    }
    __syncthreads();

    // GEMM2: h2[li][ph..ph+15], K = 128  (unchanged, verified)
    const int ph = (t & 1) << 4;
    float acc2[16];
    #pragma unroll
    for (int j = 0; j < 16; j++) acc2[j] = bf2_s[ph + j];
    for (int k = 0; k < H1DIM; k++) {
        float a = h1s[li * 132 + k];
        #pragma unroll
        for (int j = 0; j < 16; j += 4) {
            float4 w = *(const float4*)&wf2t_s[k * H2DIM + ph + j];
            acc2[j + 0] += a * w.x; acc2[j + 1] += a * w.y;
            acc2[j + 2] += a * w.z; acc2[j + 3] += a * w.w;
        }
    }
    float fsum = 0.0f;
    #pragma unroll
    for (int j = 0; j < 16; j++) fsum += fmaxf(acc2[j], 0.0f) * wf3_s[ph + j];
    fsum += __shfl_xor_sync(0xffffffffu, fsum, 1);
    if ((t & 1) == 0)
        g_fs[(size_t)(b0 + li) * RULES + r] = fmaxf(fsum + bf3[0], 0.0f);
}

// ---------------- softmax over rules: fire[b][r] --------------------------
__global__ void softmax_kernel(float* __restrict__ fire_out) {
    int b = blockIdx.x * blockDim.x + threadIdx.x;
    if (b >= BATCH) return;
    const float* f = g_fs + (size_t)b * RULES;
    float v[RULES];
    #pragma unroll
    for (int j = 0; j < RULES; j += 4) {
        float4 t4 = *(const float4*)&f[j];
        v[j] = t4.x; v[j + 1] = t4.y; v[j + 2] = t4.z; v[j + 3] = t4.w;
    }
    float m = v[0];
    #pragma unroll
    for (int j = 1; j < RULES; j++) m = fmaxf(m, v[j]);
    float s = 0.0f;
    #pragma unroll
    for (int j = 0; j < RULES; j++) { v[j] = __expf(v[j] - m); s += v[j]; }
    float inv = 1.0f / s;
    float* o = fire_out + (size_t)b * RULES;
    #pragma unroll
    for (int j = 0; j < RULES; j += 4) {
        float4 t4 = make_float4(v[j] * inv, v[j + 1] * inv, v[j + 2] * inv, v[j + 3] * inv);
        *(float4*)&o[j] = t4;
    }
}

// ---------------- fused consequent kernel: per (rule, 128-batch tile) -----
// L1 (data @ Wc1^T) now on tf32 tensor cores. L2/L3 register-carried (verified).
// smem floats: bc1 256|bc2 64|bc3 16|wc3t 1024 | As 2560 | Bs 2112 |
//              wc2t_chunk 4096 | c1s 128*129=16512  -> total 26640 (106560 B)
#define CONS_SMEM_FLOATS 26640
__global__ __launch_bounds__(256, 2)
void cons_kernel(const float* __restrict__ data, const float* __restrict__ bc1,
                 const float* __restrict__ bc2, const float* __restrict__ bc3) {
    extern __shared__ float sm[];
    float* bc1s   = sm;            // 256
    float* bc2s   = sm + 256;      // 64
    float* bc3s   = sm + 320;      // 16
    float* wc3t_s = sm + 336;      // [64][16] = 1024
    float* As     = sm + 1360;     // [128][20] row-major
    float* Bs     = sm + 3920;     // [16][132] k-major
    float* wc2t_s = sm + 6032;     // [64][64] chunk = 4096
    float* c1s    = sm + 10128;    // [128][129] = 16512

    const int t  = threadIdx.x;
    const int r  = blockIdx.y;
    const int b0 = blockIdx.x << 7;

    bc1s[t] = bc1[r * G1DIM + t];
    if (t < 64) bc2s[t] = bc2[r * G2DIM + t];
    if (t < 16) bc3s[t] = bc3[r * CDIM + t];
    for (int idx = t; idx < G2DIM * CDIM; idx += 256)
        wc3t_s[idx] = g_Wc3T[(size_t)r * G2DIM * CDIM + idx];
    __syncthreads();

    const int li = t >> 1, lk = (t & 1) << 3;
    const int kb = t >> 4, ob = (t & 15) << 3;
    const int lane = t & 31, wid = t >> 5;
    const int wr = wid & 3, wc = wid >> 2;
    const int gid = lane >> 2, tig = lane & 3;
    const int gh = (t & 1) << 5;                 // L2/L3 col group: 0 or 32
    const float* wc1t = g_Wc1T + (size_t)r * FDIM * G1DIM;
    const float* wc2t = g_Wc2T + (size_t)r * G1DIM * G2DIM;
    const float* dp_base = data + (size_t)(b0 + li) * FDIM + lk;

    // L2 accumulators (c2 row li, cols gh..gh+31), carried across both halves
    float acc2[32];
    #pragma unroll
    for (int j = 0; j < 32; j++) acc2[j] = bc2s[gh + j];

    for (int half = 0; half < 2; half++) {
        // ---- L1 GEMM (tensor cores): output cols [half*128, +128), K = 256
        float acc[2][8][4];
        #pragma unroll
        for (int i = 0; i < 2; i++)
            #pragma unroll
            for (int j = 0; j < 8; j++)
                #pragma unroll
                for (int q = 0; q < 4; q++) acc[i][j][q] = 0.0f;

        float dv[8];
        float4 wv0, wv1;
        {   // prologue
            float4 v0 = *(const float4*)(dp_base);
            float4 v1 = *(const float4*)(dp_base + 4);
            dv[0]=v0.x; dv[1]=v0.y; dv[2]=v0.z; dv[3]=v0.w;
            dv[4]=v1.x; dv[5]=v1.y; dv[6]=v1.z; dv[7]=v1.w;
            const float* wp = wc1t + (size_t)kb * G1DIM + (half << 7) + ob;
            wv0 = *(const float4*)wp; wv1 = *(const float4*)(wp + 4);
        }
        for (int k0 = 0; k0 < FDIM; k0 += 16) {
            *(float4*)&As[li * AST + lk] =
                make_float4(f2tf32(dv[0]), f2tf32(dv[1]), f2tf32(dv[2]), f2tf32(dv[3]));
            *(float4*)&As[li * AST + lk + 4] =
                make_float4(f2tf32(dv[4]), f2tf32(dv[5]), f2tf32(dv[6]), f2tf32(dv[7]));
            *(float4*)&Bs[kb * BST + ob] =
                make_float4(f2tf32(wv0.x), f2tf32(wv0.y), f2tf32(wv0.z), f2tf32(wv0.w));
            *(float4*)&Bs[kb * BST + ob + 4] =
                make_float4(f2tf32(wv1.x), f2tf32(wv1.y), f2tf32(wv1.z), f2tf32(wv1.w));
            __syncthreads();
            if (k0 + 16 < FDIM) {
                float4 v0 = *(const float4*)(dp_base + k0 + 16);
                float4 v1 = *(const float4*)(dp_base + k0 + 20);
                dv[0]=v0.x; dv[1]=v0.y; dv[2]=v0.z; dv[3]=v0.w;
                dv[4]=v1.x; dv[5]=v1.y; dv[6]=v1.z; dv[7]=v1.w;
                const float* wp = wc1t + (size_t)(k0 + 16 + kb) * G1DIM + (half << 7) + ob;
                wv0 = *(const float4*)wp; wv1 = *(const float4*)(wp + 4);
            }
            #pragma unroll
            for (int ks = 0; ks < 16; ks += 8) {
                uint32_t a[2][4];
                #pragma unroll
                for (int mt = 0; mt < 2; mt++) {
                    const float* ap = &As[(wr * 32 + mt * 16 + gid) * AST + ks + tig];
                    a[mt][0] = __float_as_uint(ap[0]);
                    a[mt][1] = __float_as_uint(ap[8 * AST]);
                    a[mt][2] = __float_as_uint(ap[4]);
                    a[mt][3] = __float_as_uint(ap[8 * AST + 4]);
                }
                #pragma unroll
                for (int nt = 0; nt < 8; nt++) {
                    int n0 = wc * 64 + nt * 8 + gid;
                    uint32_t bb0 = __float_as_uint(Bs[(ks + tig) * BST + n0]);
                    uint32_t bb1 = __float_as_uint(Bs[(ks + tig + 4) * BST + n0]);
                    MMA_TF32(acc[0][nt], a[0], bb0, bb1);
                    MMA_TF32(acc[1][nt], a[1], bb0, bb1);
                }
            }
            __syncthreads();
        }
        // epilogue: bias + ELU -> c1s (this half's 128 cols at offset 0..127)
        #pragma unroll
        for (int mt = 0; mt < 2; mt++) {
            int r0 = wr * 32 + mt * 16 + gid;
            #pragma unroll
            for (int nt = 0; nt < 8; nt++) {
                int c0 = wc * 64 + nt * 8 + 2 * tig;
                #pragma unroll
                for (int q = 0; q < 4; q++) {
                    int rr = r0 + ((q >> 1) << 3);       // +8 for c2,c3
                    int cc = c0 + (q & 1);
                    float x = acc[mt][nt][q] + bc1s[(half << 7) + cc];
                    c1s[rr * 129 + cc] = (x > 0.0f) ? x : (__expf(x) - 1.0f);
                }
            }
        }
        __syncthreads();   // c1s half fully written before L2 reads

        // ---- L2 partial: k range [half*128, +128) in two 64-row weight chunks
        for (int kc = 0; kc < 2; kc++) {
            const int kg = (half << 7) + (kc << 6);   // global k base of chunk
            for (int idx = t; idx < 64 * G2DIM; idx += 256)
                wc2t_s[idx] = wc2t[(size_t)kg * G2DIM + idx];
            __syncthreads();
            for (int k = 0; k < 64; k++) {
                float a = c1s[li * 129 + (kc << 6) + k];
                #pragma unroll
                for (int j = 0; j < 32; j += 4) {
                    float4 w = *(const float4*)&wc2t_s[k * G2DIM + gh + j];
                    acc2[j + 0] += a * w.x; acc2[j + 1] += a * w.y;
                    acc2[j + 2] += a * w.z; acc2[j + 3] += a * w.w;
                }
            }
            __syncthreads();   // before wc2t_s overwrite / c1s overwrite next half
        }
    }

    // ---- ELU on c2 (full K=256 accumulated, bias included at init) ----
    #pragma unroll
    for (int j = 0; j < 32; j++)
        acc2[j] = (acc2[j] > 0.0f) ? acc2[j] : (__expf(acc2[j]) - 1.0f);

    // ---- L3 from registers: c3[li][c] = sum_g c2[li][g] * Wc3T[g][c] ----
    float acc3[16];
    #pragma unroll
    for (int c = 0; c < 16; c++) acc3[c] = 0.0f;
    for (int g = 0; g < 32; g++) {
        float a = acc2[g];
        const float* wrow = &wc3t_s[(gh + g) * CDIM];
        #pragma unroll
        for (int c = 0; c < 16; c += 4) {
            float4 w = *(const float4*)&wrow[c];
            acc3[c + 0] += a * w.x; acc3[c + 1] += a * w.y;
            acc3[c + 2] += a * w.z; acc3[c + 3] += a * w.w;
        }
    }
    // combine the two g-halves held by the even/odd thread pair
    #pragma unroll
    for (int c = 0; c < 16; c++)
        acc3[c] += __shfl_xor_sync(0xffffffffu, acc3[c], 1);

    const int ch = (t & 1) << 3;
    float* op = g_c3 + ((size_t)((r << 14) + b0 + li)) * CDIM + ch;
    float4 o0 = make_float4(fmaxf(acc3[ch + 0] + bc3s[ch + 0], 0.f),
                            fmaxf(acc3[ch + 1] + bc3s[ch + 1], 0.f),
                            fmaxf(acc3[ch + 2] + bc3s[ch + 2], 0.f),
                            fmaxf(acc3[ch + 3] + bc3s[ch + 3], 0.f));
    float4 o1 = make_float4(fmaxf(acc3[ch + 4] + bc3s[ch + 4], 0.f),
                            fmaxf(acc3[ch + 5] + bc3s[ch + 5], 0.f),
                            fmaxf(acc3[ch + 6] + bc3s[ch + 6], 0.f),
                            fmaxf(acc3[ch + 7] + bc3s[ch + 7], 0.f));
    *(float4*)op       = o0;
    *(float4*)(op + 4) = o1;
}

// ---------------- weighted reduction: out[b][c] = sum_r fire[b][r]*c3[r][b][c]
__global__ void out_kernel(float* __restrict__ out, const float* __restrict__ fire) {
    int idx = blockIdx.x * blockDim.x + threadIdx.x;   // B*C/4 = 65536 threads
    int b  = idx >> 2;
    int c4 = (idx & 3) << 2;
    const float* fb = fire + (size_t)b * RULES;
    float4 acc = make_float4(0.f, 0.f, 0.f, 0.f);
    #pragma unroll
    for (int r = 0; r < RULES; r++) {
        float w = fb[r];
        float4 v = *(const float4*)&g_c3[((size_t)(r << 14) + b) * CDIM + c4];
        acc.x += w * v.x; acc.y += w * v.y; acc.z += w * v.z; acc.w += w * v.w;
    }
    *(float4*)&out[(size_t)b * CDIM + c4] = acc;
}

// ---------------- launch --------------------------------------------------
extern "C" void kernel_launch(void* const* d_in, const int* in_sizes, int n_in,
                              void* d_out, int out_size) {
    const float* data  = (const float*)d_in[0];
    const float* proto = (const float*)d_in[1];
    const float* var   = (const float*)d_in[2];
    const float* Wf1   = (const float*)d_in[3];
    const float* bf1   = (const float*)d_in[4];
    const float* Wf2   = (const float*)d_in[5];
    const float* bf2   = (const float*)d_in[6];
    const float* Wf3   = (const float*)d_in[7];
    const float* bf3   = (const float*)d_in[8];
    const float* Wc1   = (const float*)d_in[9];
    const float* bc1   = (const float*)d_in[10];
    const float* Wc2   = (const float*)d_in[11];
    const float* bc2   = (const float*)d_in[12];
    const float* Wc3   = (const float*)d_in[13];
    const float* bc3   = (const float*)d_in[14];
    float* out = (float*)d_out;

    // output layout: outputs [B,C] flattened first, then fire_strength [B,R]
    float* fire_dst;
    if (out_size >= BATCH * CDIM + BATCH * RULES) {
        fire_dst = out + BATCH * CDIM;
    } else {
        // fallback: only outputs requested; keep fire in scratch
        cudaGetSymbolAddress((void**)&fire_dst, g_fire_scratch);
    }

    // opt-in large dynamic smem (idempotent; host-side, not stream-ordered)
    cudaFuncSetAttribute(fs_kernel, cudaFuncAttributeMaxDynamicSharedMemorySize,
                         FS_SMEM_FLOATS * 4);
    cudaFuncSetAttribute(cons_kernel, cudaFuncAttributeMaxDynamicSharedMemorySize,
                         CONS_SMEM_FLOATS * 4);

    float *wf1t, *wf2t, *wc1t, *wc2t, *wc3t;
    cudaGetSymbolAddress((void**)&wf1t, g_Wf1T);
    cudaGetSymbolAddress((void**)&wf2t, g_Wf2T);
    cudaGetSymbolAddress((void**)&wc1t, g_Wc1T);
    cudaGetSymbolAddress((void**)&wc2t, g_Wc2T);
    cudaGetSymbolAddress((void**)&wc3t, g_Wc3T);

    dim3 tb(32, 8);
    transpose_k<<<dim3(8, 4, 1),  tb>>>(Wf1, wf1t, H1DIM, FDIM);
    transpose_k<<<dim3(4, 1, 1),  tb>>>(Wf2, wf2t, H2DIM, H1DIM);
    transpose_k<<<dim3(8, 8, 32), tb>>>(Wc1, wc1t, G1DIM, FDIM);
    transpose_k<<<dim3(8, 2, 32), tb>>>(Wc2, wc2t, G2DIM, G1DIM);
    transpose_k<<<dim3(2, 1, 32), tb>>>(Wc3, wc3t, CDIM, G2DIM);

    fs_kernel<<<dim3(BATCH / 128, RULES), 256, FS_SMEM_FLOATS * 4>>>(
        data, proto, var, bf1, bf2, Wf3, bf3);
    softmax_kernel<<<BATCH / 256, 256>>>(fire_dst);
    cons_kernel<<<dim3(BATCH / 128, RULES), 256, CONS_SMEM_FLOATS * 4>>>(
        data, bc1, bc2, bc3);
    out_kernel<<<(BATCH * CDIM / 4) / 256, 256>>>(out, fire_dst);
}